// round 1
// baseline (speedup 1.0000x reference)
#include <cuda_runtime.h>
#include <cstdint>

#define BATCH 8
#define NANCH 32768
#define NCLS  81
#define NC    80          // foreground classes
#define TOPM  200
#define NMS_TH  0.45f
#define CONF_TH 0.01f

// ---------------- scratch (static device globals; no allocations) ----------
__device__ float  g_scores[(size_t)BATCH * NC * NANCH];   // masked probs, [b][c][n]
__device__ float4 g_boxes [(size_t)BATCH * NANCH];        // decoded boxes
__device__ float  g_kept  [(size_t)BATCH * NC * TOPM];    // post-NMS scores (0 if dropped)
__device__ float4 g_cand  [(size_t)BATCH * NC * TOPM];    // candidate boxes
__device__ unsigned long long g_cutoff[BATCH];            // global top-200 composite cutoff

// ===========================================================================
// Kernel 1: softmax over 81 classes + box decode; write transposed masked
// scores [b][c][n] for contiguous top-k reads.
// ===========================================================================
__global__ void __launch_bounds__(256)
k_softmax_decode(const float* __restrict__ loc,
                 const float* __restrict__ conf,
                 const float* __restrict__ dbox)
{
    __shared__ float sm[128 * NCLS];     // 41472 B
    __shared__ float sinv[128];

    const int blk = blockIdx.x;                    // B*N/128 blocks
    const int b   = blk / (NANCH / 128);
    const int n0  = (blk % (NANCH / 128)) * 128;

    // stage 128 rows of conf (contiguous chunk) into smem, vectorized
    const float4* src4 = reinterpret_cast<const float4*>(
        conf + ((size_t)b * NANCH + n0) * NCLS);
    float4* sm4 = reinterpret_cast<float4*>(sm);
    for (int i = threadIdx.x; i < (128 * NCLS) / 4; i += 256)
        sm4[i] = src4[i];
    __syncthreads();

    const int r = threadIdx.x;
    if (r < 128) {
        // softmax: max, exp in place, sum
        float m = -1e30f;
        for (int c = 0; c < NCLS; c++) m = fmaxf(m, sm[r * NCLS + c]);
        float s = 0.f;
        for (int c = 0; c < NCLS; c++) {
            float e = expf(sm[r * NCLS + c] - m);
            sm[r * NCLS + c] = e;
            s += e;
        }
        sinv[r] = 1.0f / s;

        // box decode for this row
        const int n = n0 + r;
        float4 l = reinterpret_cast<const float4*>(loc)[(size_t)b * NANCH + n];
        float4 d = reinterpret_cast<const float4*>(dbox)[n];
        float cx = d.x + l.x * 0.1f * d.z;
        float cy = d.y + l.y * 0.1f * d.w;
        float w  = d.z * expf(l.z * 0.2f);
        float h  = d.w * expf(l.w * 0.2f);
        float x1 = cx - w * 0.5f;
        float y1 = cy - h * 0.5f;
        float x2 = x1 + w;
        float y2 = y1 + h;
        float4 o;
        o.x = fminf(fmaxf(x1, 0.f), 1.f);
        o.y = fminf(fmaxf(y1, 0.f), 1.f);
        o.z = fminf(fmaxf(x2, 0.f), 1.f);
        o.w = fminf(fmaxf(y2, 0.f), 1.f);
        g_boxes[(size_t)b * NANCH + n] = o;
    }
    __syncthreads();

    // transposed masked-score writes: i = c*128 + rr  -> coalesced per class
    for (int i = threadIdx.x; i < 128 * NC; i += 256) {
        const int c  = i >> 7;       // 0..79  (class c+1)
        const int rr = i & 127;
        float p = sm[rr * NCLS + (c + 1)] * sinv[rr];
        g_scores[((size_t)b * NC + c) * NANCH + (n0 + rr)] = (p > CONF_TH) ? p : -1.0f;
    }
}

// ===========================================================================
// Kernel 2: per-(b,class) exact stable top-200 (2-level radix select over
// float bits + bitonic sort of boundary set) fused with greedy NMS.
// ===========================================================================
__global__ void __launch_bounds__(256)
k_topk_nms()
{
    __shared__ unsigned int hist[2048];
    __shared__ unsigned int psum[256];
    __shared__ unsigned long long buf[2048];
    __shared__ unsigned int s_cnt;
    __shared__ int s_b1, s_chi, s_pref;
    __shared__ float4 s_bx[TOPM];
    __shared__ float  s_area[TOPM];
    __shared__ float  s_sc[TOPM];
    __shared__ int    s_active[TOPM];
    __shared__ int    s_keep[TOPM];

    const int bc  = blockIdx.x;           // b*80 + c
    const int b   = bc / NC;
    const int tid = threadIdx.x;
    const float* data = g_scores + (size_t)bc * NANCH;

    // ---- pass 1: histogram on bits>>21 (sign+exp+2 mantissa) ----
    for (int i = tid; i < 2048; i += 256) hist[i] = 0;
    __syncthreads();
    for (int i = tid; i < NANCH; i += 256) {
        float v = data[i];
        if (v > 0.f) atomicAdd(&hist[__float_as_uint(v) >> 21], 1u);
    }
    __syncthreads();
    { unsigned int s = 0; for (int j = 0; j < 8; j++) s += hist[tid * 8 + j]; psum[tid] = s; }
    __syncthreads();
    if (tid == 0) {
        int acc = 0, b1 = -1, chi = 0;
        for (int t = 255; t >= 0; t--) {
            if (acc + (int)psum[t] >= TOPM) {
                for (int bb = t * 8 + 7; bb >= t * 8; bb--) {
                    int cnt = (int)hist[bb];
                    if (acc + cnt >= TOPM) { b1 = bb; chi = acc; break; }
                    acc += cnt;
                }
                break;
            }
            acc += (int)psum[t];
        }
        s_b1 = b1; s_chi = chi; s_cnt = 0;
    }
    __syncthreads();
    const int b1 = s_b1;

    // ---- pass 2: refine 11 more bits within bin b1 ----
    if (b1 >= 0) {
        for (int i = tid; i < 2048; i += 256) hist[i] = 0;
        __syncthreads();
        for (int i = tid; i < NANCH; i += 256) {
            float v = data[i];
            if (v > 0.f) {
                unsigned int u = __float_as_uint(v);
                if ((int)(u >> 21) == b1) atomicAdd(&hist[(u >> 10) & 2047], 1u);
            }
        }
        __syncthreads();
        { unsigned int s = 0; for (int j = 0; j < 8; j++) s += hist[tid * 8 + j]; psum[tid] = s; }
        __syncthreads();
        if (tid == 0) {
            const int target = TOPM - s_chi;
            int acc = 0, b2 = 0;
            for (int t = 255; t >= 0; t--) {
                if (acc + (int)psum[t] >= target) {
                    for (int bb = t * 8 + 7; bb >= t * 8; bb--) {
                        int cnt = (int)hist[bb];
                        if (acc + cnt >= target) { b2 = bb; break; }
                        acc += cnt;
                    }
                    break;
                }
                acc += (int)psum[t];
            }
            s_pref = (b1 << 11) | b2;
        }
        __syncthreads();
    }
    const int pref = (b1 >= 0) ? s_pref : 0;

    // ---- pass 3: gather boundary superset as composite keys ----
    for (int i = tid; i < NANCH; i += 256) {
        float v = data[i];
        if (v > 0.f) {
            unsigned int u = __float_as_uint(v);
            if (b1 < 0 || (int)(u >> 10) >= pref) {
                unsigned int p = atomicAdd(&s_cnt, 1u);
                if (p < 2048)
                    buf[p] = ((unsigned long long)u << 32) |
                             (unsigned long long)(0xFFFFFFFFu - (unsigned int)i);
            }
        }
    }
    __syncthreads();
    const unsigned int G = min(s_cnt, 2048u);
    for (int i = tid; i < 2048; i += 256) if ((unsigned)i >= G) buf[i] = 0ull;
    __syncthreads();

    // ---- bitonic sort, descending, size 2048 (keys unique where nonzero) ----
    for (int k = 2; k <= 2048; k <<= 1) {
        for (int j = k >> 1; j > 0; j >>= 1) {
            for (int t = tid; t < 2048; t += 256) {
                int ixj = t ^ j;
                if (ixj > t) {
                    unsigned long long a = buf[t], c2 = buf[ixj];
                    bool dirDesc = ((t & k) == 0);
                    if ((a < c2) == dirDesc) { buf[t] = c2; buf[ixj] = a; }
                }
            }
            __syncthreads();
        }
    }

    // ---- materialize top-200 candidates ----
    if (tid < TOPM) {
        unsigned long long cmp = buf[tid];
        float sc; float4 bx;
        if ((unsigned)tid < G && cmp != 0ull) {
            sc = __uint_as_float((unsigned int)(cmp >> 32));
            unsigned int idx = 0xFFFFFFFFu - (unsigned int)(cmp & 0xFFFFFFFFull);
            bx = g_boxes[(size_t)b * NANCH + idx];
        } else {
            sc = -1.0f; bx = make_float4(0.f, 0.f, 0.f, 0.f);
        }
        s_sc[tid]     = sc;
        s_bx[tid]     = bx;
        s_area[tid]   = (bx.z - bx.x) * (bx.w - bx.y);
        s_active[tid] = (sc > CONF_TH) ? 1 : 0;
    }
    __syncthreads();

    // ---- greedy NMS (matches scan semantics; NaN IoU suppresses) ----
    for (int i = 0; i < TOPM; i++) {
        int k_i = s_active[i];
        if (tid == i) s_keep[i] = k_i;
        __syncthreads();
        if (k_i && tid < TOPM) {
            float4 bi = s_bx[i];
            float4 bj = s_bx[tid];
            float xx1 = fmaxf(bi.x, bj.x);
            float yy1 = fmaxf(bi.y, bj.y);
            float xx2 = fminf(bi.z, bj.z);
            float yy2 = fminf(bi.w, bj.w);
            float inter = fmaxf(xx2 - xx1, 0.f) * fmaxf(yy2 - yy1, 0.f);
            float uni   = s_area[tid] - inter + s_area[i];
            float iou   = inter / uni;
            if (!(iou <= NMS_TH)) s_active[tid] = 0;
        }
        __syncthreads();
    }

    if (tid < TOPM) {
        g_kept[(size_t)bc * TOPM + tid] = s_keep[tid] ? s_sc[tid] : 0.f;
        g_cand[(size_t)bc * TOPM + tid] = s_bx[tid];
    }
}

// ===========================================================================
// Kernel 3: per-batch global top-200 composite cutoff over 16000 kept scores.
// ===========================================================================
__global__ void __launch_bounds__(256)
k_global_cutoff()
{
    __shared__ unsigned int hist[2048];
    __shared__ unsigned int psum[256];
    __shared__ unsigned long long buf[2048];
    __shared__ unsigned int s_cnt;
    __shared__ int s_b1, s_chi, s_pref;

    const int b   = blockIdx.x;
    const int tid = threadIdx.x;
    const int NTOT = NC * TOPM;          // 16000
    const float* data = g_kept + (size_t)b * NTOT;

    for (int i = tid; i < 2048; i += 256) hist[i] = 0;
    __syncthreads();
    for (int i = tid; i < NTOT; i += 256) {
        float v = data[i];
        if (v > 0.f) atomicAdd(&hist[__float_as_uint(v) >> 21], 1u);
    }
    __syncthreads();
    { unsigned int s = 0; for (int j = 0; j < 8; j++) s += hist[tid * 8 + j]; psum[tid] = s; }
    __syncthreads();
    if (tid == 0) {
        int acc = 0, b1 = -1, chi = 0;
        for (int t = 255; t >= 0; t--) {
            if (acc + (int)psum[t] >= TOPM) {
                for (int bb = t * 8 + 7; bb >= t * 8; bb--) {
                    int cnt = (int)hist[bb];
                    if (acc + cnt >= TOPM) { b1 = bb; chi = acc; break; }
                    acc += cnt;
                }
                break;
            }
            acc += (int)psum[t];
        }
        s_b1 = b1; s_chi = chi; s_cnt = 0;
    }
    __syncthreads();
    const int b1 = s_b1;

    if (b1 >= 0) {
        for (int i = tid; i < 2048; i += 256) hist[i] = 0;
        __syncthreads();
        for (int i = tid; i < NTOT; i += 256) {
            float v = data[i];
            if (v > 0.f) {
                unsigned int u = __float_as_uint(v);
                if ((int)(u >> 21) == b1) atomicAdd(&hist[(u >> 10) & 2047], 1u);
            }
        }
        __syncthreads();
        { unsigned int s = 0; for (int j = 0; j < 8; j++) s += hist[tid * 8 + j]; psum[tid] = s; }
        __syncthreads();
        if (tid == 0) {
            const int target = TOPM - s_chi;
            int acc = 0, b2 = 0;
            for (int t = 255; t >= 0; t--) {
                if (acc + (int)psum[t] >= target) {
                    for (int bb = t * 8 + 7; bb >= t * 8; bb--) {
                        int cnt = (int)hist[bb];
                        if (acc + cnt >= target) { b2 = bb; break; }
                        acc += cnt;
                    }
                    break;
                }
                acc += (int)psum[t];
            }
            s_pref = (b1 << 11) | b2;
        }
        __syncthreads();
    }
    const int pref = (b1 >= 0) ? s_pref : 0;

    for (int i = tid; i < NTOT; i += 256) {
        float v = data[i];
        if (v > 0.f) {
            unsigned int u = __float_as_uint(v);
            if (b1 < 0 || (int)(u >> 10) >= pref) {
                unsigned int p = atomicAdd(&s_cnt, 1u);
                if (p < 2048)
                    buf[p] = ((unsigned long long)u << 32) |
                             (unsigned long long)(0xFFFFFFFFu - (unsigned int)i);
            }
        }
    }
    __syncthreads();
    const unsigned int G = min(s_cnt, 2048u);
    for (int i = tid; i < 2048; i += 256) if ((unsigned)i >= G) buf[i] = 0ull;
    __syncthreads();

    for (int k = 2; k <= 2048; k <<= 1) {
        for (int j = k >> 1; j > 0; j >>= 1) {
            for (int t = tid; t < 2048; t += 256) {
                int ixj = t ^ j;
                if (ixj > t) {
                    unsigned long long a = buf[t], c2 = buf[ixj];
                    bool dirDesc = ((t & k) == 0);
                    if ((a < c2) == dirDesc) { buf[t] = c2; buf[ixj] = a; }
                }
            }
            __syncthreads();
        }
    }

    if (tid == 0)
        g_cutoff[b] = (b1 >= 0) ? buf[TOPM - 1] : 0ull;   // <200 positives -> keep all
}

// ===========================================================================
// Kernel 4: output writer — zero everything, then compact survivors to front.
// out layout: [B][81][200][5], class 0 all zeros.
// ===========================================================================
__global__ void __launch_bounds__(256)
k_write(float* __restrict__ out)
{
    __shared__ unsigned int wcnt[8];
    const int c   = blockIdx.x;   // 0..80
    const int b   = blockIdx.y;
    const int tid = threadIdx.x;

    float* o = out + ((size_t)(b * NCLS + c)) * TOPM * 5;
    for (int i = tid; i < TOPM * 5; i += 256) o[i] = 0.f;
    if (c == 0) return;
    __syncthreads();

    const int c80 = c - 1;
    const size_t base = ((size_t)b * NC + c80) * TOPM;
    const unsigned long long cut = g_cutoff[b];

    float v = 0.f; bool flag = false; float4 bx = make_float4(0.f, 0.f, 0.f, 0.f);
    if (tid < TOPM) {
        v = g_kept[base + tid];
        if (v > 0.f) {
            unsigned long long comp =
                ((unsigned long long)__float_as_uint(v) << 32) |
                (unsigned long long)(0xFFFFFFFFu - (unsigned int)(c80 * TOPM + tid));
            flag = (comp >= cut);
        }
        if (flag) bx = g_cand[base + tid];
    }
    unsigned int ball = __ballot_sync(0xFFFFFFFFu, flag);
    const int wid = tid >> 5, lane = tid & 31;
    if (lane == 0) wcnt[wid] = __popc(ball);
    __syncthreads();
    int off = 0;
    for (int w = 0; w < wid; w++) off += (int)wcnt[w];
    if (flag) {
        int pos = off + __popc(ball & ((1u << lane) - 1));
        float* p = o + (size_t)pos * 5;
        p[0] = v; p[1] = bx.x; p[2] = bx.y; p[3] = bx.z; p[4] = bx.w;
    }
}

// ===========================================================================
extern "C" void kernel_launch(void* const* d_in, const int* in_sizes, int n_in,
                              void* d_out, int out_size)
{
    const float* loc  = (const float*)d_in[0];
    const float* conf = (const float*)d_in[1];
    const float* dbox = (const float*)d_in[2];
    float* out = (float*)d_out;

    k_softmax_decode<<<BATCH * (NANCH / 128), 256>>>(loc, conf, dbox);
    k_topk_nms<<<BATCH * NC, 256>>>();
    k_global_cutoff<<<BATCH, 256>>>();
    k_write<<<dim3(NCLS, BATCH), 256>>>(out);
}

// round 2
// speedup vs baseline: 1.1090x; 1.1090x over previous
#include <cuda_runtime.h>
#include <cstdint>

#define BATCH 8
#define NANCH 32768
#define NCLS  81
#define NC    80          // foreground classes
#define TOPM  200
#define NMS_TH  0.45f
#define CONF_TH 0.01f
#define NCHUNK  7         // ceil(224/32) bit chunks covering TOPM=200

// ---------------- scratch (static device globals; no allocations) ----------
__device__ float  g_scores[(size_t)BATCH * NC * NANCH];   // masked probs, [b][c][n]
__device__ float4 g_boxes [(size_t)BATCH * NANCH];        // decoded boxes
__device__ float  g_kept  [(size_t)BATCH * NC * TOPM];    // post-NMS scores (0 if dropped)
__device__ float4 g_cand  [(size_t)BATCH * NC * TOPM];    // candidate boxes
__device__ unsigned long long g_cutoff[BATCH];            // global top-200 composite cutoff

// bin of a score in (CONF_TH, 1): 16-bit float-bit prefix, guaranteed in [0,2048)
__device__ __forceinline__ int score_bin(float v) {
    int b = (int)(__float_as_uint(v) >> 15) - 30720;
    return min(max(b, 0), 2047);
}

// ===========================================================================
// Kernel 1: softmax over 81 classes + box decode; 2 threads per row.
// Writes transposed masked scores [b][c][n] (0 if below threshold).
// ===========================================================================
__global__ void __launch_bounds__(256)
k_softmax_decode(const float* __restrict__ loc,
                 const float* __restrict__ conf,
                 const float* __restrict__ dbox)
{
    __shared__ float sm[128 * NCLS];     // 41472 B
    __shared__ float sinv[128];

    const int blk = blockIdx.x;                    // B*N/128 blocks
    const int b   = blk / (NANCH / 128);
    const int n0  = (blk % (NANCH / 128)) * 128;
    const int tid = threadIdx.x;

    // stage 128 rows of conf (contiguous) into smem, vectorized
    const float4* src4 = reinterpret_cast<const float4*>(
        conf + ((size_t)b * NANCH + n0) * NCLS);
    float4* sm4 = reinterpret_cast<float4*>(sm);
    for (int i = tid; i < (128 * NCLS) / 4; i += 256)
        sm4[i] = src4[i];

    // box decode (independent of smem) - threads 0..127, one row each
    if (tid < 128) {
        const int n = n0 + tid;
        float4 l = reinterpret_cast<const float4*>(loc)[(size_t)b * NANCH + n];
        float4 d = reinterpret_cast<const float4*>(dbox)[n];
        float cx = d.x + l.x * 0.1f * d.z;
        float cy = d.y + l.y * 0.1f * d.w;
        float w  = d.z * expf(l.z * 0.2f);
        float h  = d.w * expf(l.w * 0.2f);
        float x1 = cx - w * 0.5f;
        float y1 = cy - h * 0.5f;
        float4 o;
        o.x = fminf(fmaxf(x1, 0.f), 1.f);
        o.y = fminf(fmaxf(y1, 0.f), 1.f);
        o.z = fminf(fmaxf(x1 + w, 0.f), 1.f);
        o.w = fminf(fmaxf(y1 + h, 0.f), 1.f);
        g_boxes[(size_t)b * NANCH + n] = o;
    }
    __syncthreads();

    // softmax: pair (2r, 2r+1) handles row r; halves = classes [0,41) / [41,81)
    {
        const int r    = tid >> 1;
        const int half = tid & 1;
        const int c0   = half ? 41 : 0;
        const int cn   = half ? 40 : 41;
        float* row = sm + r * NCLS;

        float m = -1e30f;
        #pragma unroll 8
        for (int c = 0; c < cn; c++) m = fmaxf(m, row[c0 + c]);
        m = fmaxf(m, __shfl_xor_sync(0xFFFFFFFFu, m, 1));

        float s = 0.f;
        #pragma unroll 8
        for (int c = 0; c < cn; c++) {
            float e = expf(row[c0 + c] - m);
            row[c0 + c] = e;
            s += e;
        }
        s += __shfl_xor_sync(0xFFFFFFFFu, s, 1);
        if (!half) sinv[r] = 1.0f / s;
    }
    __syncthreads();

    // transposed masked-score writes: coalesced per class
    for (int i = tid; i < 128 * NC; i += 256) {
        const int c  = i >> 7;       // 0..79  (class c+1)
        const int rr = i & 127;
        float p = sm[rr * NCLS + (c + 1)] * sinv[rr];
        g_scores[((size_t)b * NC + c) * NANCH + (n0 + rr)] = (p > CONF_TH) ? p : 0.0f;
    }
}

// ===========================================================================
// Kernel 2: per-(b,class) exact stable top-200 via single-pass 16-bit radix
// select + dynamic-size bitonic sort; NMS via parallel bit-matrix + warp scan.
// ===========================================================================
__global__ void __launch_bounds__(256)
k_topk_nms()
{
    __shared__ unsigned int hist[2048];
    __shared__ unsigned int psum[256];
    __shared__ unsigned long long buf[2048];
    __shared__ unsigned int s_cnt;
    __shared__ int s_bin, s_g, s_P;
    __shared__ float4 s_bx[TOPM];
    __shared__ float  s_area[TOPM];
    __shared__ float  s_sc[TOPM];
    __shared__ unsigned int s_sup[TOPM * NCHUNK];  // suppression bit matrix
    __shared__ unsigned int s_act[NCHUNK];
    __shared__ int s_keep[TOPM];

    const int bc  = blockIdx.x;           // b*80 + c
    const int b   = bc / NC;
    const int tid = threadIdx.x;
    const float* data = g_scores + (size_t)bc * NANCH;
    const float4* d4  = reinterpret_cast<const float4*>(data);

    // ---- pass 1: single 16-bit-prefix histogram ----
    for (int i = tid; i < 2048; i += 256) hist[i] = 0;
    __syncthreads();
    for (int i = tid; i < NANCH / 4; i += 256) {
        float4 v = d4[i];
        if (v.x > CONF_TH) atomicAdd(&hist[score_bin(v.x)], 1u);
        if (v.y > CONF_TH) atomicAdd(&hist[score_bin(v.y)], 1u);
        if (v.z > CONF_TH) atomicAdd(&hist[score_bin(v.z)], 1u);
        if (v.w > CONF_TH) atomicAdd(&hist[score_bin(v.w)], 1u);
    }
    __syncthreads();
    { unsigned int s = 0;
      #pragma unroll
      for (int j = 0; j < 8; j++) s += hist[tid * 8 + j];
      psum[tid] = s; }
    __syncthreads();
    if (tid == 0) {
        int acc = 0, binq = -1;
        for (int t = 255; t >= 0; t--) {
            if (acc + (int)psum[t] >= TOPM) {
                for (int bb = t * 8 + 7; bb >= t * 8; bb--) {
                    int cnt = (int)hist[bb];
                    if (acc + cnt >= TOPM) { binq = bb; break; }
                    acc += cnt;
                }
                break;
            }
            acc += (int)psum[t];
        }
        s_bin = binq;            // -1 => fewer than 200 positives: take all
        s_cnt = 0;
    }
    __syncthreads();
    const int binq = s_bin;

    // ---- pass 2: gather boundary superset as composite keys ----
    for (int i = tid; i < NANCH / 4; i += 256) {
        float4 v = d4[i];
        const float vs[4] = {v.x, v.y, v.z, v.w};
        #pragma unroll
        for (int j = 0; j < 4; j++) {
            float val = vs[j];
            if (val > CONF_TH && (binq < 0 || score_bin(val) >= binq)) {
                unsigned int p = atomicAdd(&s_cnt, 1u);
                if (p < 2048) {
                    unsigned int idx = 4 * i + j;
                    buf[p] = ((unsigned long long)__float_as_uint(val) << 32) |
                             (unsigned long long)(0xFFFFFFFFu - idx);
                }
            }
        }
    }
    __syncthreads();
    if (tid == 0) {
        int g = (int)min(s_cnt, 2048u);
        int P = 256;
        while (P < g) P <<= 1;
        s_g = g; s_P = P;
    }
    __syncthreads();
    const int g = s_g, P = s_P;
    for (int i = tid; i < P; i += 256) if (i >= g) buf[i] = 0ull;
    __syncthreads();

    // ---- bitonic sort, descending, dynamic size P (pow2 in [256,2048]) ----
    for (int k = 2; k <= P; k <<= 1) {
        for (int j = k >> 1; j > 0; j >>= 1) {
            for (int t = tid; t < P; t += 256) {
                int ixj = t ^ j;
                if (ixj > t) {
                    unsigned long long a = buf[t], c2 = buf[ixj];
                    bool dirDesc = ((t & k) == 0);
                    if ((a < c2) == dirDesc) { buf[t] = c2; buf[ixj] = a; }
                }
            }
            __syncthreads();
        }
    }

    // ---- materialize top-200 candidates ----
    bool val_f = false;
    if (tid < TOPM) {
        float sc; float4 bx;
        if (tid < g) {
            unsigned long long cmp = buf[tid];
            sc = __uint_as_float((unsigned int)(cmp >> 32));
            unsigned int idx = 0xFFFFFFFFu - (unsigned int)(cmp & 0xFFFFFFFFull);
            bx = g_boxes[(size_t)b * NANCH + idx];
            val_f = true;
        } else {
            sc = 0.f; bx = make_float4(0.f, 0.f, 0.f, 0.f);
        }
        s_sc[tid]   = sc;
        s_bx[tid]   = bx;
        s_area[tid] = (bx.z - bx.x) * (bx.w - bx.y);
        s_keep[tid] = 0;
    }
    // active-init bitmask (warps 0..6 cover indices 0..223)
    {
        unsigned int bm = __ballot_sync(0xFFFFFFFFu, val_f);
        if ((tid & 31) == 0 && (tid >> 5) < NCHUNK) s_act[tid >> 5] = bm;
    }
    __syncthreads();

    // ---- suppression bit matrix: bit j of row i set iff !(IoU(i,j) <= th) ----
    for (int task = tid; task < TOPM * NCHUNK; task += 256) {
        const int i     = task / NCHUNK;
        const int chunk = task % NCHUNK;
        const float4 bi = s_bx[i];
        const float  ai = s_area[i];
        unsigned int bits = 0;
        const int jmax = min(32, TOPM - chunk * 32);
        #pragma unroll 4
        for (int bb = 0; bb < jmax; bb++) {
            const int j = chunk * 32 + bb;
            float4 bj = s_bx[j];
            float xx1 = fmaxf(bi.x, bj.x);
            float yy1 = fmaxf(bi.y, bj.y);
            float xx2 = fminf(bi.z, bj.z);
            float yy2 = fminf(bi.w, bj.w);
            float inter = fmaxf(xx2 - xx1, 0.f) * fmaxf(yy2 - yy1, 0.f);
            float uni   = s_area[j] - inter + ai;
            float iou   = inter / uni;
            if (!(iou <= NMS_TH)) bits |= (1u << bb);
        }
        s_sup[task] = bits;
    }
    __syncthreads();

    // ---- greedy scan, single warp, no block barriers ----
    if (tid < 32) {
        unsigned int act = (tid < NCHUNK) ? s_act[tid] : 0u;
        for (int i = 0; i < TOPM; i++) {
            unsigned int owner_act = __shfl_sync(0xFFFFFFFFu, act, i >> 5);
            bool k = (owner_act >> (i & 31)) & 1u;
            if (k) {
                if (tid < NCHUNK) act &= ~s_sup[i * NCHUNK + tid];
                if (tid == 0) s_keep[i] = 1;
            }
        }
    }
    __syncthreads();

    if (tid < TOPM) {
        g_kept[(size_t)bc * TOPM + tid] = s_keep[tid] ? s_sc[tid] : 0.f;
        g_cand[(size_t)bc * TOPM + tid] = s_bx[tid];
    }
}

// ===========================================================================
// Kernel 3: per-batch global top-200 composite cutoff over 16000 kept scores.
// Same single-pass radix select + dynamic bitonic.
// ===========================================================================
__global__ void __launch_bounds__(256)
k_global_cutoff()
{
    __shared__ unsigned int hist[2048];
    __shared__ unsigned int psum[256];
    __shared__ unsigned long long buf[2048];
    __shared__ unsigned int s_cnt;
    __shared__ int s_bin, s_g, s_P;

    const int b   = blockIdx.x;
    const int tid = threadIdx.x;
    const int NTOT = NC * TOPM;          // 16000
    const float* data = g_kept + (size_t)b * NTOT;
    const float4* d4  = reinterpret_cast<const float4*>(data);

    for (int i = tid; i < 2048; i += 256) hist[i] = 0;
    __syncthreads();
    for (int i = tid; i < NTOT / 4; i += 256) {
        float4 v = d4[i];
        if (v.x > 0.f) atomicAdd(&hist[score_bin(v.x)], 1u);
        if (v.y > 0.f) atomicAdd(&hist[score_bin(v.y)], 1u);
        if (v.z > 0.f) atomicAdd(&hist[score_bin(v.z)], 1u);
        if (v.w > 0.f) atomicAdd(&hist[score_bin(v.w)], 1u);
    }
    __syncthreads();
    { unsigned int s = 0;
      #pragma unroll
      for (int j = 0; j < 8; j++) s += hist[tid * 8 + j];
      psum[tid] = s; }
    __syncthreads();
    if (tid == 0) {
        int acc = 0, binq = -1;
        for (int t = 255; t >= 0; t--) {
            if (acc + (int)psum[t] >= TOPM) {
                for (int bb = t * 8 + 7; bb >= t * 8; bb--) {
                    int cnt = (int)hist[bb];
                    if (acc + cnt >= TOPM) { binq = bb; break; }
                    acc += cnt;
                }
                break;
            }
            acc += (int)psum[t];
        }
        s_bin = binq;
        s_cnt = 0;
    }
    __syncthreads();
    const int binq = s_bin;

    if (binq < 0) {                      // fewer than 200 positives: keep all
        if (tid == 0) g_cutoff[b] = 0ull;
        return;
    }

    for (int i = tid; i < NTOT / 4; i += 256) {
        float4 v = d4[i];
        const float vs[4] = {v.x, v.y, v.z, v.w};
        #pragma unroll
        for (int j = 0; j < 4; j++) {
            float val = vs[j];
            if (val > 0.f && score_bin(val) >= binq) {
                unsigned int p = atomicAdd(&s_cnt, 1u);
                if (p < 2048) {
                    unsigned int idx = 4 * i + j;
                    buf[p] = ((unsigned long long)__float_as_uint(val) << 32) |
                             (unsigned long long)(0xFFFFFFFFu - idx);
                }
            }
        }
    }
    __syncthreads();
    if (tid == 0) {
        int g = (int)min(s_cnt, 2048u);
        int P = 256;
        while (P < g) P <<= 1;
        s_g = g; s_P = P;
    }
    __syncthreads();
    const int g = s_g, P = s_P;
    for (int i = tid; i < P; i += 256) if (i >= g) buf[i] = 0ull;
    __syncthreads();

    for (int k = 2; k <= P; k <<= 1) {
        for (int j = k >> 1; j > 0; j >>= 1) {
            for (int t = tid; t < P; t += 256) {
                int ixj = t ^ j;
                if (ixj > t) {
                    unsigned long long a = buf[t], c2 = buf[ixj];
                    bool dirDesc = ((t & k) == 0);
                    if ((a < c2) == dirDesc) { buf[t] = c2; buf[ixj] = a; }
                }
            }
            __syncthreads();
        }
    }

    if (tid == 0)
        g_cutoff[b] = buf[TOPM - 1];
}

// ===========================================================================
// Kernel 4: output writer — zero everything, then compact survivors to front.
// out layout: [B][81][200][5], class 0 all zeros.
// ===========================================================================
__global__ void __launch_bounds__(256)
k_write(float* __restrict__ out)
{
    __shared__ unsigned int wcnt[8];
    const int c   = blockIdx.x;   // 0..80
    const int b   = blockIdx.y;
    const int tid = threadIdx.x;

    float* o = out + ((size_t)(b * NCLS + c)) * TOPM * 5;
    for (int i = tid; i < TOPM * 5; i += 256) o[i] = 0.f;
    if (c == 0) return;
    __syncthreads();

    const int c80 = c - 1;
    const size_t base = ((size_t)b * NC + c80) * TOPM;
    const unsigned long long cut = g_cutoff[b];

    float v = 0.f; bool flag = false; float4 bx = make_float4(0.f, 0.f, 0.f, 0.f);
    if (tid < TOPM) {
        v = g_kept[base + tid];
        if (v > 0.f) {
            unsigned long long comp =
                ((unsigned long long)__float_as_uint(v) << 32) |
                (unsigned long long)(0xFFFFFFFFu - (unsigned int)(c80 * TOPM + tid));
            flag = (comp >= cut);
        }
        if (flag) bx = g_cand[base + tid];
    }
    unsigned int ball = __ballot_sync(0xFFFFFFFFu, flag);
    const int wid = tid >> 5, lane = tid & 31;
    if (lane == 0) wcnt[wid] = __popc(ball);
    __syncthreads();
    int off = 0;
    for (int w = 0; w < wid; w++) off += (int)wcnt[w];
    if (flag) {
        int pos = off + __popc(ball & ((1u << lane) - 1));
        float* p = o + (size_t)pos * 5;
        p[0] = v; p[1] = bx.x; p[2] = bx.y; p[3] = bx.z; p[4] = bx.w;
    }
}

// ===========================================================================
extern "C" void kernel_launch(void* const* d_in, const int* in_sizes, int n_in,
                              void* d_out, int out_size)
{
    const float* loc  = (const float*)d_in[0];
    const float* conf = (const float*)d_in[1];
    const float* dbox = (const float*)d_in[2];
    float* out = (float*)d_out;

    k_softmax_decode<<<BATCH * (NANCH / 128), 256>>>(loc, conf, dbox);
    k_topk_nms<<<BATCH * NC, 256>>>();
    k_global_cutoff<<<BATCH, 256>>>();
    k_write<<<dim3(NCLS, BATCH), 256>>>(out);
}